// round 2
// baseline (speedup 1.0000x reference)
#include <cuda_runtime.h>
#include <cstdint>

// out[n] = S * ( sum_k (x[k]-X_ZP) * y[k,n]  -  Y_ZP * sum_k (x[k]-X_ZP) )
// Exact int32 accumulation (max |sum| ~1.58e8 < 2^31).
// X_SCALE=0.0215, X_ZP=-25, Y_SCALE=0.0176, Y_ZP=18
//
// Structure (2 launches, no atomics, no zero-init):
//   gemv:     grid (N_TILES=8, SPLITS=64). Each block streams a 128-row x
//             2048-col tile of y (fully coalesced 2x int4 per thread) and
//             WRITES its partial sums to g_part[split][n] (plain STG).
//   finalize: sums the 64 partials per column + zero-point correction.

#define KDIM 8192
#define NDIM 16384
#define THREADS 256
#define COLS_PER_THREAD 8                             // 2x int4
#define COLS_PER_BLOCK (THREADS * COLS_PER_THREAD)    // 2048
#define N_TILES (NDIM / COLS_PER_BLOCK)               // 8
#define KCHUNK 128
#define SPLITS (KDIM / KCHUNK)                        // 64

__device__ int g_part[SPLITS][NDIM];   // per-split partial dot products
__device__ int g_sa_part[SPLITS];      // per-split sum of (x[k]+25)

__global__ __launch_bounds__(THREADS) void gemv_kernel(
    const int* __restrict__ x, const int* __restrict__ y)
{
    __shared__ int sa[KCHUNK];
    const int tid   = threadIdx.x;
    const int split = blockIdx.y;
    const int k0    = split * KCHUNK;

    // a[k] = x[k] - X_ZP = x[k] + 25
    for (int i = tid; i < KCHUNK; i += THREADS)
        sa[i] = x[k0 + i] + 25;
    __syncthreads();

    const int n0 = blockIdx.x * COLS_PER_BLOCK + tid * COLS_PER_THREAD;
    const int4* yp = reinterpret_cast<const int4*>(y + (size_t)k0 * NDIM + n0);
    const size_t strideV = NDIM / 4;

    int a0 = 0, a1 = 0, a2 = 0, a3 = 0;
    int b0 = 0, b1 = 0, b2 = 0, b3 = 0;
    #pragma unroll 8
    for (int kk = 0; kk < KCHUNK; kk++) {
        const int a = sa[kk];
        const int4 v0 = yp[(size_t)kk * strideV + 0];
        const int4 v1 = yp[(size_t)kk * strideV + 1];
        a0 += a * v0.x;  a1 += a * v0.y;  a2 += a * v0.z;  a3 += a * v0.w;
        b0 += a * v1.x;  b1 += a * v1.y;  b2 += a * v1.z;  b3 += a * v1.w;
    }

    int4* pp = reinterpret_cast<int4*>(&g_part[split][n0]);
    pp[0] = make_int4(a0, a1, a2, a3);
    pp[1] = make_int4(b0, b1, b2, b3);

    // one n-tile per split contributes the sum-of-a partial
    if (blockIdx.x == 0 && tid < 32) {
        int s = 0;
        #pragma unroll
        for (int i = 0; i < KCHUNK / 32; i++)
            s += sa[tid + i * 32];
        #pragma unroll
        for (int o = 16; o > 0; o >>= 1)
            s += __shfl_down_sync(0xffffffffu, s, o);
        if (tid == 0) g_sa_part[split] = s;
    }
}

__global__ __launch_bounds__(THREADS) void finalize_kernel(float* __restrict__ out) {
    __shared__ int s_sa;
    const int tid = threadIdx.x;

    if (tid < 32) {
        int s = 0;
        #pragma unroll
        for (int i = 0; i < SPLITS / 32; i++)
            s += g_sa_part[tid + i * 32];
        #pragma unroll
        for (int o = 16; o > 0; o >>= 1)
            s += __shfl_down_sync(0xffffffffu, s, o);
        if (tid == 0) s_sa = s;
    }
    __syncthreads();

    const int n = blockIdx.x * THREADS + tid;
    int acc = 0;
    #pragma unroll 16
    for (int s = 0; s < SPLITS; s++)
        acc += g_part[s][n];

    const float S = (float)(0.0215 * 0.0176);
    out[n] = S * (float)(acc - 18 * s_sa);
}

extern "C" void kernel_launch(void* const* d_in, const int* in_sizes, int n_in,
                              void* d_out, int out_size) {
    const int* x = (const int*)d_in[0];   // [K]
    const int* y = (const int*)d_in[1];   // [K, N]
    float* out = (float*)d_out;           // [N]

    dim3 grid(N_TILES, SPLITS);
    gemv_kernel<<<grid, THREADS>>>(x, y);
    finalize_kernel<<<NDIM / THREADS, THREADS>>>(out);
}

// round 3
// speedup vs baseline: 1.0493x; 1.0493x over previous
#include <cuda_runtime.h>
#include <cstdint>

// out[n] = S * ( sum_k (x[k]-X_ZP) * y[k,n]  -  Y_ZP * sum_k (x[k]-X_ZP) )
// Exact int32 accumulation (max |sum| ~1.58e8 < 2^31).
// X_SCALE=0.0215, X_ZP=-25, Y_SCALE=0.0176, Y_ZP=18
//
// gemv:     grid (16 n-tiles x 64 K-splits) = 1024 blocks x 256 thr.
//           Each thread owns 4 cols (one int4/row), streams a 128-row chunk,
//           stores its partial (plain STG, no atomics, no zero-init).
// finalize: 256 blocks x 64 thr, each thread reduces 64 partials (L2 hits).

#define KDIM 8192
#define NDIM 16384
#define THREADS 256
#define COLS_PER_THREAD 4
#define COLS_PER_BLOCK (THREADS * COLS_PER_THREAD)    // 1024
#define N_TILES (NDIM / COLS_PER_BLOCK)               // 16
#define KCHUNK 128
#define SPLITS (KDIM / KCHUNK)                        // 64

#define FIN_THREADS 64
#define FIN_BLOCKS (NDIM / FIN_THREADS)               // 256

__device__ int g_part[SPLITS][NDIM];   // per-split partial dot products
__device__ int g_sa_part[SPLITS];      // per-split sum of (x[k]+25)

__global__ __launch_bounds__(THREADS) void gemv_kernel(
    const int* __restrict__ x, const int* __restrict__ y)
{
    __shared__ int sa[KCHUNK];
    const int tid   = threadIdx.x;
    const int split = blockIdx.y;
    const int k0    = split * KCHUNK;

    // a[k] = x[k] - X_ZP = x[k] + 25
    if (tid < KCHUNK)
        sa[tid] = x[k0 + tid] + 25;
    __syncthreads();

    const int n0 = blockIdx.x * COLS_PER_BLOCK + tid * COLS_PER_THREAD;
    const int4* yp = reinterpret_cast<const int4*>(y + (size_t)k0 * NDIM + n0);
    const size_t strideV = NDIM / 4;

    int a0 = 0, a1 = 0, a2 = 0, a3 = 0;
    #pragma unroll 8
    for (int kk = 0; kk < KCHUNK; kk++) {
        const int a = sa[kk];
        const int4 v = __ldcs(&yp[(size_t)kk * strideV]);
        a0 += a * v.x;  a1 += a * v.y;  a2 += a * v.z;  a3 += a * v.w;
    }

    *reinterpret_cast<int4*>(&g_part[split][n0]) = make_int4(a0, a1, a2, a3);

    // one n-tile per split contributes the sum-of-a partial
    if (blockIdx.x == 0 && tid < 32) {
        int s = 0;
        #pragma unroll
        for (int i = 0; i < KCHUNK / 32; i++)
            s += sa[tid + i * 32];
        #pragma unroll
        for (int o = 16; o > 0; o >>= 1)
            s += __shfl_down_sync(0xffffffffu, s, o);
        if (tid == 0) g_sa_part[split] = s;
    }
}

__global__ __launch_bounds__(FIN_THREADS) void finalize_kernel(float* __restrict__ out) {
    __shared__ int s_sa;
    const int tid = threadIdx.x;

    if (tid < 32) {
        int s = g_sa_part[tid] + g_sa_part[tid + 32];
        #pragma unroll
        for (int o = 16; o > 0; o >>= 1)
            s += __shfl_down_sync(0xffffffffu, s, o);
        if (tid == 0) s_sa = s;
    }
    __syncthreads();

    const int n = blockIdx.x * FIN_THREADS + tid;
    int acc = 0;
    #pragma unroll
    for (int s = 0; s < SPLITS; s++)
        acc += g_part[s][n];

    const float S = (float)(0.0215 * 0.0176);
    out[n] = S * (float)(acc - 18 * s_sa);
}

extern "C" void kernel_launch(void* const* d_in, const int* in_sizes, int n_in,
                              void* d_out, int out_size) {
    const int* x = (const int*)d_in[0];   // [K]
    const int* y = (const int*)d_in[1];   // [K, N]
    float* out = (float*)d_out;           // [N]

    dim3 grid(N_TILES, SPLITS);
    gemv_kernel<<<grid, THREADS>>>(x, y);
    finalize_kernel<<<FIN_BLOCKS, FIN_THREADS>>>(out);
}